// round 2
// baseline (speedup 1.0000x reference)
#include <cuda_runtime.h>

#define NMAX 100000
#define EMAX 1600000
#define F 128

// ---------------- scratch (device globals; no allocation allowed) ----------------
__device__ double g_doutw[NMAX];           // weighted out-degree (sum of w over src)
__device__ double g_dinw[NMAX];            // weighted in-degree  (sum of w over dst)
__device__ int    g_cntin[NMAX];           // unweighted in-degree
__device__ int    g_cntout[NMAX];          // unweighted out-degree
__device__ float  g_wraw[EMAX];            // raw edge weight
__device__ int    g_rowstart[NMAX + 1];    // CSR (by dst) row starts
__device__ int    g_cursor[NMAX];          // fill cursors
__device__ float  g_normin[NMAX];          // deg_in^-0.5  (clamped >= 1)
__device__ float  g_normout[NMAX];         // deg_out^-0.5 (clamped >= 1)
__device__ float  g_rdoutw[NMAX];          // rsqrt(weighted out-degree)
__device__ float  g_rdinw[NMAX];           // rsqrt(weighted in-degree)
__device__ int2   g_csr[EMAX];             // {src, float_bits(w' = w_norm * normout[src])}
__device__ float  g_h [(size_t)NMAX * F];  // x @ W1          (no row scaling!)
__device__ float  g_h1[(size_t)NMAX * F];  // relu(agg1*norm_in + b1)
__device__ float  g_h2[(size_t)NMAX * F];  // g_h1 @ W2

// ---------------- f32x2 packed-FMA helpers ----------------
__device__ __forceinline__ void ffma2(unsigned long long& d, unsigned long long a,
                                      unsigned long long b) {
    asm("fma.rn.f32x2 %0, %1, %2, %0;" : "+l"(d) : "l"(a), "l"(b));
}
__device__ __forceinline__ unsigned long long pack2(float x, float y) {
    unsigned long long r;
    asm("mov.b64 %0, {%1, %2};" : "=l"(r) : "f"(x), "f"(y));
    return r;
}
__device__ __forceinline__ float2 unpack2(unsigned long long v) {
    float2 r;
    asm("mov.b64 {%0, %1}, %2;" : "=f"(r.x), "=f"(r.y) : "l"(v));
    return r;
}

// ---------------- K0: zero accumulators ----------------
__global__ void k_zero(int N) {
    int i = blockIdx.x * blockDim.x + threadIdx.x;
    if (i < N) {
        g_doutw[i] = 0.0; g_dinw[i] = 0.0;
        g_cntin[i] = 0;   g_cntout[i] = 0;
    }
}

// ---------------- K1: edge weights + degree sums ----------------
__global__ void k_edge_w(const float* __restrict__ ef, const float* __restrict__ Wef,
                         const float* __restrict__ bef,
                         const int* __restrict__ src, const int* __restrict__ dst, int E) {
    int e = blockIdx.x * blockDim.x + threadIdx.x;
    if (e >= E) return;
    const float4* p = (const float4*)(ef + (size_t)e * 16);
    float acc = __ldg(bef);
#pragma unroll
    for (int q = 0; q < 4; q++) {
        float4 v = __ldg(p + q);
        acc += v.x * __ldg(Wef + q * 4 + 0) + v.y * __ldg(Wef + q * 4 + 1)
             + v.z * __ldg(Wef + q * 4 + 2) + v.w * __ldg(Wef + q * 4 + 3);
    }
    g_wraw[e] = acc;
    int s = src[e], d = dst[e];
    atomicAdd(&g_doutw[s], (double)acc);
    atomicAdd(&g_dinw[d],  (double)acc);
    atomicAdd(&g_cntout[s], 1);
    atomicAdd(&g_cntin[d],  1);
}

// ---------------- K2: single-block exclusive scan of in-degrees -> rowstart ----------------
__global__ void k_scan(int N, int E) {
    __shared__ int warpsums[32];
    __shared__ int s_carry;
    int tid = threadIdx.x;
    int lane = tid & 31, wid = tid >> 5;
    if (tid == 0) s_carry = 0;
    __syncthreads();
    for (int base = 0; base < N; base += 1024) {
        int i = base + tid;
        int v = (i < N) ? g_cntin[i] : 0;
        int x = v;
#pragma unroll
        for (int o = 1; o < 32; o <<= 1) {
            int y = __shfl_up_sync(0xffffffffu, x, o);
            if (lane >= o) x += y;
        }
        if (lane == 31) warpsums[wid] = x;
        __syncthreads();
        if (wid == 0) {
            int w = warpsums[lane];
#pragma unroll
            for (int o = 1; o < 32; o <<= 1) {
                int y = __shfl_up_sync(0xffffffffu, w, o);
                if (lane >= o) w += y;
            }
            warpsums[lane] = w;
        }
        __syncthreads();
        int excl = (x - v) + (wid > 0 ? warpsums[wid - 1] : 0) + s_carry;
        if (i < N) g_rowstart[i] = excl;
        __syncthreads();
        if (tid == 0) s_carry += warpsums[31];
        __syncthreads();
    }
    if (tid == 0) g_rowstart[N] = E;
}

// ---------------- K3: node-side normalizers + cursors ----------------
__global__ void k_node(int N) {
    int i = blockIdx.x * blockDim.x + threadIdx.x;
    if (i >= N) return;
    int cin = g_cntin[i], cout = g_cntout[i];
    g_normin[i]  = rsqrtf((float)(cin  > 1 ? cin  : 1));
    g_normout[i] = rsqrtf((float)(cout > 1 ? cout : 1));
    float dw = (float)g_doutw[i];
    float iw = (float)g_dinw[i];
    g_rdoutw[i] = dw > 0.f ? rsqrtf(dw) : 0.f;
    g_rdinw[i]  = iw > 0.f ? rsqrtf(iw) : 0.f;
    g_cursor[i] = g_rowstart[i];
}

// ---------------- K4: fill CSR (by dst); normout[src] folded into the weight ----------------
__global__ void k_fill(const int* __restrict__ src, const int* __restrict__ dst, int E) {
    int e = blockIdx.x * blockDim.x + threadIdx.x;
    if (e >= E) return;
    int s = src[e], d = dst[e];
    int pos = atomicAdd(&g_cursor[d], 1);
    float w = g_wraw[e] * g_rdoutw[s] * g_rdinw[d] * g_normout[s];
    g_csr[pos] = make_int2(s, __float_as_int(w));
}

// ---------------- K5: GEMM  C[N,128] = A[N,128] @ W[128,128]  via packed f32x2 FMA --------
// BM=64, BN=128, BK=16, 256 threads, 8x4 microtile per thread (4 M-pairs x 4 cols).
__global__ __launch_bounds__(256)
void k_gemm(const float* __restrict__ A, const float* __restrict__ W,
            float* __restrict__ C, int N) {
    __shared__ float As[16][68];   // stride 68: 16B-aligned rows, modest store conflicts
    __shared__ float Bs[16][128];

    int tid = threadIdx.x;
    int block_row = blockIdx.x * 64;
    int tx = tid & 31;       // col group: cols tx*4 .. tx*4+3
    int ty = tid >> 5;       // row group: rows ty*8 .. ty*8+7

    int am = tid >> 2;             // 0..63 (A row within tile)
    int ak = (tid & 3) * 4;        // 0,4,8,12 (A k offset)
    int bk = tid >> 5;             // 0..7
    int bj = (tid & 31) * 4;       // 0..124

    unsigned long long accp[4][4];
#pragma unroll
    for (int p = 0; p < 4; p++)
#pragma unroll
        for (int c = 0; c < 4; c++) accp[p][c] = 0ull;

    for (int k0 = 0; k0 < 128; k0 += 16) {
        int arow = block_row + am;
        float4 av = make_float4(0.f, 0.f, 0.f, 0.f);
        if (arow < N) av = *(const float4*)(A + (size_t)arow * F + k0 + ak);
        As[ak + 0][am] = av.x; As[ak + 1][am] = av.y;
        As[ak + 2][am] = av.z; As[ak + 3][am] = av.w;

        *(float4*)&Bs[bk][bj]     = *(const float4*)(W + (size_t)(k0 + bk) * F + bj);
        *(float4*)&Bs[bk + 8][bj] = *(const float4*)(W + (size_t)(k0 + bk + 8) * F + bj);
        __syncthreads();

#pragma unroll
        for (int kk = 0; kk < 16; kk++) {
            const float* arp = &As[kk][ty * 8];
            ulonglong2 ap0 = *(const ulonglong2*)(arp);      // pairs (m0,m1),(m2,m3)
            ulonglong2 ap1 = *(const ulonglong2*)(arp + 4);  // pairs (m4,m5),(m6,m7)
            float4 bv = *(const float4*)&Bs[kk][tx * 4];
            unsigned long long b0 = pack2(bv.x, bv.x);
            unsigned long long b1 = pack2(bv.y, bv.y);
            unsigned long long b2 = pack2(bv.z, bv.z);
            unsigned long long b3 = pack2(bv.w, bv.w);
            ffma2(accp[0][0], ap0.x, b0); ffma2(accp[0][1], ap0.x, b1);
            ffma2(accp[0][2], ap0.x, b2); ffma2(accp[0][3], ap0.x, b3);
            ffma2(accp[1][0], ap0.y, b0); ffma2(accp[1][1], ap0.y, b1);
            ffma2(accp[1][2], ap0.y, b2); ffma2(accp[1][3], ap0.y, b3);
            ffma2(accp[2][0], ap1.x, b0); ffma2(accp[2][1], ap1.x, b1);
            ffma2(accp[2][2], ap1.x, b2); ffma2(accp[2][3], ap1.x, b3);
            ffma2(accp[3][0], ap1.y, b0); ffma2(accp[3][1], ap1.y, b1);
            ffma2(accp[3][2], ap1.y, b2); ffma2(accp[3][3], ap1.y, b3);
        }
        __syncthreads();
    }

#pragma unroll
    for (int p = 0; p < 4; p++) {
        float2 c0 = unpack2(accp[p][0]);
        float2 c1 = unpack2(accp[p][1]);
        float2 c2 = unpack2(accp[p][2]);
        float2 c3 = unpack2(accp[p][3]);
        int row0 = block_row + ty * 8 + 2 * p;
        if (row0 < N) {
            float4 o; o.x = c0.x; o.y = c1.x; o.z = c2.x; o.w = c3.x;
            *(float4*)(C + (size_t)row0 * F + tx * 4) = o;
        }
        if (row0 + 1 < N) {
            float4 o; o.x = c0.y; o.y = c1.y; o.z = c2.y; o.w = c3.y;
            *(float4*)(C + (size_t)(row0 + 1) * F + tx * 4) = o;
        }
    }
}

// ---------------- K6: warp-per-node CSR aggregation ----------------
// MODE 1: out = relu(acc*norm_in + b)    (layer 1; normout already folded into CSR w)
// MODE 0: out = acc*norm_in + b          (layer 2; final output)
template <int MODE>
__global__ __launch_bounds__(256)
void k_agg(const float* __restrict__ H, const float* __restrict__ bias,
           float* __restrict__ OUT, int N) {
    int gw = (blockIdx.x * blockDim.x + threadIdx.x) >> 5;
    if (gw >= N) return;
    int lane = threadIdx.x & 31;
    int i0 = g_rowstart[gw], i1 = g_rowstart[gw + 1];

    // double accumulation, two independent chains per component: order-insensitive
    // to the float ulp (CSR fill order is atomic-nondeterministic) while halving
    // the DADD dependency chain.
    double a0 = 0.0, a1 = 0.0, a2 = 0.0, a3 = 0.0;
    double b0 = 0.0, b1 = 0.0, b2 = 0.0, b3 = 0.0;
    int i = i0;
#pragma unroll 2
    for (; i + 1 < i1; i += 2) {
        int2 eA = g_csr[i];
        int2 eB = g_csr[i + 1];
        float wA = __int_as_float(eA.y);
        float wB = __int_as_float(eB.y);
        float4 hA = *(const float4*)(H + (size_t)eA.x * F + lane * 4);
        float4 hB = *(const float4*)(H + (size_t)eB.x * F + lane * 4);
        a0 += (double)(wA * hA.x); a1 += (double)(wA * hA.y);
        a2 += (double)(wA * hA.z); a3 += (double)(wA * hA.w);
        b0 += (double)(wB * hB.x); b1 += (double)(wB * hB.y);
        b2 += (double)(wB * hB.z); b3 += (double)(wB * hB.w);
    }
    if (i < i1) {
        int2 eA = g_csr[i];
        float wA = __int_as_float(eA.y);
        float4 hA = *(const float4*)(H + (size_t)eA.x * F + lane * 4);
        a0 += (double)(wA * hA.x); a1 += (double)(wA * hA.y);
        a2 += (double)(wA * hA.z); a3 += (double)(wA * hA.w);
    }
    float ni = g_normin[gw];
    float4 bb = *(const float4*)(bias + lane * 4);
    float o0 = (float)(a0 + b0) * ni + bb.x;
    float o1 = (float)(a1 + b1) * ni + bb.y;
    float o2 = (float)(a2 + b2) * ni + bb.z;
    float o3 = (float)(a3 + b3) * ni + bb.w;
    if (MODE == 1) {
        o0 = fmaxf(o0, 0.f); o1 = fmaxf(o1, 0.f);
        o2 = fmaxf(o2, 0.f); o3 = fmaxf(o3, 0.f);
    }
    float4 o; o.x = o0; o.y = o1; o.z = o2; o.w = o3;
    *(float4*)(OUT + (size_t)gw * F + lane * 4) = o;
}

// ---------------- host ----------------
extern "C" void kernel_launch(void* const* d_in, const int* in_sizes, int n_in,
                              void* d_out, int out_size) {
    const float* node_feats = (const float*)d_in[0];
    const float* edge_feats = (const float*)d_in[1];
    const float* W_ef       = (const float*)d_in[2];
    const float* b_ef       = (const float*)d_in[3];
    const float* W1         = (const float*)d_in[4];
    const float* b1         = (const float*)d_in[5];
    const float* W2         = (const float*)d_in[6];
    const float* b2         = (const float*)d_in[7];
    const int*   src        = (const int*)d_in[8];
    const int*   dst        = (const int*)d_in[9];
    int N = in_sizes[0] / F;
    int E = in_sizes[8];
    float* out = (float*)d_out;

    float *ph, *ph1, *ph2;
    cudaGetSymbolAddress((void**)&ph,  g_h);
    cudaGetSymbolAddress((void**)&ph1, g_h1);
    cudaGetSymbolAddress((void**)&ph2, g_h2);

    int nbN = (N + 255) / 256;
    int nbE = (E + 255) / 256;
    int nbG = (N + 63) / 64;
    int nbA = (N * 32 + 255) / 256;

    // Launch order chosen so our 4th launch (the one ncu's fixed -s captures)
    // is the GEMM. gemm1 has no dependency on graph statistics now that
    // normout[src] is folded into the CSR weight.
    k_zero  <<<nbN, 256>>>(N);                             // 0
    k_edge_w<<<nbE, 256>>>(edge_feats, W_ef, b_ef, src, dst, E); // 1
    k_scan  <<<1, 1024>>>(N, E);                           // 2
    k_gemm  <<<nbG, 256>>>(node_feats, W1, ph,  N);        // 3  <- profiled
    k_node  <<<nbN, 256>>>(N);                             // 4
    k_fill  <<<nbE, 256>>>(src, dst, E);                   // 5
    k_agg<1><<<nbA, 256>>>(ph,  b1, ph1, N);               // 6
    k_gemm  <<<nbG, 256>>>(ph1, W2, ph2, N);               // 7
    k_agg<0><<<nbA, 256>>>(ph2, b2, out, N);               // 8
}

// round 3
// speedup vs baseline: 3.2185x; 3.2185x over previous
#include <cuda_runtime.h>

#define NMAX 100000
#define EMAX 1600000
#define F 128

// ---------------- scratch (device globals; zero-initialized at load) ----------------
__device__ unsigned long long g_doutw64[NMAX]; // fixed-point (2^52) weighted out-degree
__device__ unsigned long long g_dinw64[NMAX];  // fixed-point weighted in-degree
__device__ int    g_cntin[NMAX];               // unweighted in-degree
__device__ int    g_cntout[NMAX];              // unweighted out-degree
__device__ int    g_done[NMAX];                // row completion counters (fill_sort)
__device__ float  g_wraw[EMAX];                // raw edge weight
__device__ int    g_rowstart[NMAX + 1];        // CSR (by dst) row starts
__device__ int    g_cursor[NMAX];              // fill cursors
__device__ float  g_srcscale[NMAX];            // rdoutw * normout  (src-side folded scale)
__device__ float  g_dscale[NMAX];              // rdinw * normin    (dst-side folded scale)
__device__ unsigned long long g_csr[EMAX];     // (src<<32)|wbits, each row canonically sorted
__device__ float  g_a1[(size_t)NMAX * F];      // aggregated node_feats  (* dscale)
__device__ float  g_h1[(size_t)NMAX * F];      // relu(a1 @ W1 + b1)
__device__ float  g_a2[(size_t)NMAX * F];      // aggregated h1          (* dscale)

#define FIX_SCALE_F   0x1p52f
#define FIX_INV_F     0x1p-52f

// ---------------- f32x2 packed-FMA helpers ----------------
__device__ __forceinline__ void ffma2(unsigned long long& d, unsigned long long a,
                                      unsigned long long b) {
    asm("fma.rn.f32x2 %0, %1, %2, %0;" : "+l"(d) : "l"(a), "l"(b));
}
__device__ __forceinline__ unsigned long long pack2(float x, float y) {
    unsigned long long r;
    asm("mov.b64 %0, {%1, %2};" : "=l"(r) : "f"(x), "f"(y));
    return r;
}
__device__ __forceinline__ float2 unpack2(unsigned long long v) {
    float2 r;
    asm("mov.b64 {%0, %1}, %2;" : "=f"(r.x), "=f"(r.y) : "l"(v));
    return r;
}

// ---------------- K1: edge weights + integer degree sums ----------------
__global__ void k_edge_w(const float* __restrict__ ef, const float* __restrict__ Wef,
                         const float* __restrict__ bef,
                         const int* __restrict__ src, const int* __restrict__ dst, int E) {
    int e = blockIdx.x * blockDim.x + threadIdx.x;
    if (e >= E) return;
    const float4* p = (const float4*)(ef + (size_t)e * 16);
    float acc = __ldg(bef);
#pragma unroll
    for (int q = 0; q < 4; q++) {
        float4 v = __ldg(p + q);
        acc += v.x * __ldg(Wef + q * 4 + 0) + v.y * __ldg(Wef + q * 4 + 1)
             + v.z * __ldg(Wef + q * 4 + 2) + v.w * __ldg(Wef + q * 4 + 3);
    }
    g_wraw[e] = acc;
    unsigned long long fx = __float2ull_rn(acc * FIX_SCALE_F);  // w > 0 by construction
    int s = src[e], d = dst[e];
    atomicAdd(&g_doutw64[s], fx);
    atomicAdd(&g_dinw64[d],  fx);
    atomicAdd(&g_cntout[s], 1);
    atomicAdd(&g_cntin[d],  1);
}

// ---------------- K2: single-block scan + node normalizers + cursors ----------------
__global__ void k_scan_node(int N, int E) {
    __shared__ int warpsums[32];
    __shared__ int s_carry;
    int tid = threadIdx.x;
    int lane = tid & 31, wid = tid >> 5;
    if (tid == 0) s_carry = 0;
    __syncthreads();
    for (int base = 0; base < N; base += 1024) {
        int i = base + tid;
        int v = (i < N) ? g_cntin[i] : 0;
        int x = v;
#pragma unroll
        for (int o = 1; o < 32; o <<= 1) {
            int y = __shfl_up_sync(0xffffffffu, x, o);
            if (lane >= o) x += y;
        }
        if (lane == 31) warpsums[wid] = x;
        __syncthreads();
        if (wid == 0) {
            int w = warpsums[lane];
#pragma unroll
            for (int o = 1; o < 32; o <<= 1) {
                int y = __shfl_up_sync(0xffffffffu, w, o);
                if (lane >= o) w += y;
            }
            warpsums[lane] = w;
        }
        __syncthreads();
        int excl = (x - v) + (wid > 0 ? warpsums[wid - 1] : 0) + s_carry;
        if (i < N) {
            g_rowstart[i] = excl;
            g_cursor[i] = excl;
            int cout = g_cntout[i];
            float dw = __ull2float_rn(g_doutw64[i]) * FIX_INV_F;
            float iw = __ull2float_rn(g_dinw64[i])  * FIX_INV_F;
            float rdo = dw > 0.f ? rsqrtf(dw) : 0.f;
            float rdi = iw > 0.f ? rsqrtf(iw) : 0.f;
            g_srcscale[i] = rdo * rsqrtf((float)(cout > 1 ? cout : 1));
            g_dscale[i]   = rdi * rsqrtf((float)(v > 1 ? v : 1));
        }
        __syncthreads();
        if (tid == 0) s_carry += warpsums[31];
        __syncthreads();
    }
    if (tid == 0) g_rowstart[N] = E;
}

// ---------------- K3: fill CSR + canonical per-row sort ----------------
// Last thread to complete a row sorts it by the packed 64-bit key -> CSR content
// is deterministic even though atomic fill order is not.
__global__ void k_fill_sort(const int* __restrict__ src, const int* __restrict__ dst, int E) {
    int e = blockIdx.x * blockDim.x + threadIdx.x;
    if (e >= E) return;
    int s = src[e], d = dst[e];
    float w = g_wraw[e] * __ldg(&g_srcscale[s]);
    unsigned long long key = ((unsigned long long)(unsigned)s << 32)
                           | (unsigned)__float_as_int(w);
    int pos = atomicAdd(&g_cursor[d], 1);
    g_csr[pos] = key;
    __threadfence();
    int r0 = __ldg(&g_rowstart[d]);
    int len = __ldg(&g_rowstart[d + 1]) - r0;
    int old = atomicAdd(&g_done[d], 1);
    if (old == len - 1) {
        __threadfence();
        if (len <= 128) {
            unsigned long long buf[128];
            for (int j = 0; j < len; j++) buf[j] = g_csr[r0 + j];
            for (int j = 1; j < len; j++) {           // insertion sort
                unsigned long long k = buf[j];
                int t = j - 1;
                while (t >= 0 && buf[t] > k) { buf[t + 1] = buf[t]; t--; }
                buf[t + 1] = k;
            }
            for (int j = 0; j < len; j++) g_csr[r0 + j] = buf[j];
        } else {                                       // rare fallback: in-place
            for (int j = 1; j < len; j++) {
                unsigned long long k = g_csr[r0 + j];
                int t = j - 1;
                while (t >= 0 && g_csr[r0 + t] > k) { g_csr[r0 + t + 1] = g_csr[r0 + t]; t--; }
                g_csr[r0 + t + 1] = k;
            }
        }
    }
}

// ---------------- K4: warp-per-node CSR aggregation (plain float; CSR is canonical) ----
__global__ __launch_bounds__(256)
void k_agg(const float* __restrict__ H, float* __restrict__ OUT, int N) {
    int gw = (blockIdx.x * blockDim.x + threadIdx.x) >> 5;
    if (gw >= N) return;
    int lane = threadIdx.x & 31;
    int i0 = __ldg(&g_rowstart[gw]), i1 = __ldg(&g_rowstart[gw + 1]);

    float a0 = 0.f, a1 = 0.f, a2 = 0.f, a3 = 0.f;
    int i = i0;
    for (; i + 1 < i1; i += 2) {
        unsigned long long kA = __ldg(&g_csr[i]);
        unsigned long long kB = __ldg(&g_csr[i + 1]);
        float wA = __int_as_float((int)(unsigned)kA);
        float wB = __int_as_float((int)(unsigned)kB);
        const float4* pA = (const float4*)(H + ((size_t)(kA >> 32)) * F) + lane;
        const float4* pB = (const float4*)(H + ((size_t)(kB >> 32)) * F) + lane;
        float4 hA = __ldg(pA);
        float4 hB = __ldg(pB);
        a0 += wA * hA.x; a1 += wA * hA.y; a2 += wA * hA.z; a3 += wA * hA.w;
        a0 += wB * hB.x; a1 += wB * hB.y; a2 += wB * hB.z; a3 += wB * hB.w;
    }
    if (i < i1) {
        unsigned long long kA = __ldg(&g_csr[i]);
        float wA = __int_as_float((int)(unsigned)kA);
        float4 hA = __ldg((const float4*)(H + ((size_t)(kA >> 32)) * F) + lane);
        a0 += wA * hA.x; a1 += wA * hA.y; a2 += wA * hA.z; a3 += wA * hA.w;
    }
    float sc = __ldg(&g_dscale[gw]);
    float4 o; o.x = a0 * sc; o.y = a1 * sc; o.z = a2 * sc; o.w = a3 * sc;
    *(float4*)(OUT + (size_t)gw * F + lane * 4) = o;
}

// ---------------- K5: GEMM  C = A @ W (+bias, optional relu) via packed f32x2 FMA ----
// BM=64, BN=128, BK=16, 256 threads, 8x4 microtile (4 row-pairs x 4 cols).
template <int RELU>
__global__ __launch_bounds__(256)
void k_gemm(const float* __restrict__ A, const float* __restrict__ W,
            const float* __restrict__ bias, float* __restrict__ C, int N) {
    __shared__ float As[16][68];
    __shared__ float Bs[16][128];

    int tid = threadIdx.x;
    int block_row = blockIdx.x * 64;
    int tx = tid & 31;
    int ty = tid >> 5;

    int am = tid >> 2;
    int ak = (tid & 3) * 4;
    int bk = tid >> 5;
    int bj = (tid & 31) * 4;

    unsigned long long accp[4][4];
#pragma unroll
    for (int p = 0; p < 4; p++)
#pragma unroll
        for (int c = 0; c < 4; c++) accp[p][c] = 0ull;

    for (int k0 = 0; k0 < 128; k0 += 16) {
        int arow = block_row + am;
        float4 av = make_float4(0.f, 0.f, 0.f, 0.f);
        if (arow < N) av = *(const float4*)(A + (size_t)arow * F + k0 + ak);
        As[ak + 0][am] = av.x; As[ak + 1][am] = av.y;
        As[ak + 2][am] = av.z; As[ak + 3][am] = av.w;

        *(float4*)&Bs[bk][bj]     = *(const float4*)(W + (size_t)(k0 + bk) * F + bj);
        *(float4*)&Bs[bk + 8][bj] = *(const float4*)(W + (size_t)(k0 + bk + 8) * F + bj);
        __syncthreads();

#pragma unroll
        for (int kk = 0; kk < 16; kk++) {
            const float* arp = &As[kk][ty * 8];
            ulonglong2 ap0 = *(const ulonglong2*)(arp);
            ulonglong2 ap1 = *(const ulonglong2*)(arp + 4);
            float4 bv = *(const float4*)&Bs[kk][tx * 4];
            unsigned long long b0 = pack2(bv.x, bv.x);
            unsigned long long b1 = pack2(bv.y, bv.y);
            unsigned long long b2 = pack2(bv.z, bv.z);
            unsigned long long b3 = pack2(bv.w, bv.w);
            ffma2(accp[0][0], ap0.x, b0); ffma2(accp[0][1], ap0.x, b1);
            ffma2(accp[0][2], ap0.x, b2); ffma2(accp[0][3], ap0.x, b3);
            ffma2(accp[1][0], ap0.y, b0); ffma2(accp[1][1], ap0.y, b1);
            ffma2(accp[1][2], ap0.y, b2); ffma2(accp[1][3], ap0.y, b3);
            ffma2(accp[2][0], ap1.x, b0); ffma2(accp[2][1], ap1.x, b1);
            ffma2(accp[2][2], ap1.x, b2); ffma2(accp[2][3], ap1.x, b3);
            ffma2(accp[3][0], ap1.y, b0); ffma2(accp[3][1], ap1.y, b1);
            ffma2(accp[3][2], ap1.y, b2); ffma2(accp[3][3], ap1.y, b3);
        }
        __syncthreads();
    }

    float4 bv = __ldg((const float4*)(bias) + tx);
#pragma unroll
    for (int p = 0; p < 4; p++) {
        float2 c0 = unpack2(accp[p][0]);
        float2 c1 = unpack2(accp[p][1]);
        float2 c2 = unpack2(accp[p][2]);
        float2 c3 = unpack2(accp[p][3]);
        int row0 = block_row + ty * 8 + 2 * p;
        float4 o0, o1;
        o0.x = c0.x + bv.x; o0.y = c1.x + bv.y; o0.z = c2.x + bv.z; o0.w = c3.x + bv.w;
        o1.x = c0.y + bv.x; o1.y = c1.y + bv.y; o1.z = c2.y + bv.z; o1.w = c3.y + bv.w;
        if (RELU) {
            o0.x = fmaxf(o0.x, 0.f); o0.y = fmaxf(o0.y, 0.f);
            o0.z = fmaxf(o0.z, 0.f); o0.w = fmaxf(o0.w, 0.f);
            o1.x = fmaxf(o1.x, 0.f); o1.y = fmaxf(o1.y, 0.f);
            o1.z = fmaxf(o1.z, 0.f); o1.w = fmaxf(o1.w, 0.f);
        }
        if (row0 < N)     *(float4*)(C + (size_t)row0 * F + tx * 4) = o0;
        if (row0 + 1 < N) *(float4*)(C + (size_t)(row0 + 1) * F + tx * 4) = o1;
    }
}

// ---------------- K6: trailing zero (prepares counters for the NEXT replay) ----------
__global__ void k_zero_tail(int N) {
    int i = blockIdx.x * blockDim.x + threadIdx.x;
    if (i < N) {
        g_doutw64[i] = 0ull; g_dinw64[i] = 0ull;
        g_cntin[i] = 0; g_cntout[i] = 0; g_done[i] = 0;
    }
}

// ---------------- host ----------------
extern "C" void kernel_launch(void* const* d_in, const int* in_sizes, int n_in,
                              void* d_out, int out_size) {
    const float* node_feats = (const float*)d_in[0];
    const float* edge_feats = (const float*)d_in[1];
    const float* W_ef       = (const float*)d_in[2];
    const float* b_ef       = (const float*)d_in[3];
    const float* W1         = (const float*)d_in[4];
    const float* b1         = (const float*)d_in[5];
    const float* W2         = (const float*)d_in[6];
    const float* b2         = (const float*)d_in[7];
    const int*   src        = (const int*)d_in[8];
    const int*   dst        = (const int*)d_in[9];
    int N = in_sizes[0] / F;
    int E = in_sizes[8];
    float* out = (float*)d_out;

    float *pa1, *ph1, *pa2;
    cudaGetSymbolAddress((void**)&pa1, g_a1);
    cudaGetSymbolAddress((void**)&ph1, g_h1);
    cudaGetSymbolAddress((void**)&pa2, g_a2);

    int nbN = (N + 255) / 256;
    int nbE = (E + 255) / 256;
    int nbG = (N + 63) / 64;
    int nbA = (N * 32 + 255) / 256;

    // Aggregation commuted ahead of GEMM (both linear). Our launch index 3
    // (= ncu's captured launch) is the layer-1 aggregation — the suspected
    // bottleneck.
    k_edge_w   <<<nbE, 256>>>(edge_feats, W_ef, b_ef, src, dst, E); // 0
    k_scan_node<<<1, 1024>>>(N, E);                                 // 1
    k_fill_sort<<<nbE, 256>>>(src, dst, E);                         // 2
    k_agg      <<<nbA, 256>>>(node_feats, pa1, N);                  // 3  <- profiled
    k_gemm<1>  <<<nbG, 256>>>(pa1, W1, b1, ph1, N);                 // 4
    k_agg      <<<nbA, 256>>>(ph1, pa2, N);                         // 5
    k_gemm<0>  <<<nbG, 256>>>(pa2, W2, b2, out, N);                 // 6
    k_zero_tail<<<nbN, 256>>>(N);                                   // 7
}

// round 5
// speedup vs baseline: 4.9493x; 1.5378x over previous
#include <cuda_runtime.h>

#define NMAX 100000
#define EMAX 1600000
#define F 128
#define SCAN_BLK 1024
#define NBLK_SCAN ((NMAX + SCAN_BLK - 1) / SCAN_BLK)   // 98

// ---------------- scratch (device globals; zero-initialized at load) ----------------
__device__ unsigned long long g_doutw64[NMAX]; // fixed-point (2^52) weighted out-degree
__device__ unsigned long long g_dinw64[NMAX];  // fixed-point weighted in-degree
__device__ int    g_cntin[NMAX];               // unweighted in-degree
__device__ int    g_cntout[NMAX];              // unweighted out-degree
__device__ float  g_wraw[EMAX];                // raw edge weight
__device__ int    g_rowstart[NMAX + 1];        // CSR (by dst) row starts
__device__ int    g_cursor[NMAX];              // fill cursors
__device__ float  g_srcscale[NMAX];            // rdoutw * normout  (src-side folded scale)
__device__ float  g_dscale[NMAX];              // rdinw * normin    (dst-side folded scale)
__device__ int    g_blocksum[NBLK_SCAN];       // scan phase-1 block sums
__device__ unsigned long long g_csr[EMAX];     // (src<<32)|wbits, rows canonically sorted
__device__ float  g_a1[(size_t)NMAX * F];      // aggregated node_feats  (* dscale)
__device__ float  g_h1[(size_t)NMAX * F];      // relu(a1 @ W1 + b1)
__device__ float  g_a2[(size_t)NMAX * F];      // aggregated h1          (* dscale)

#define FIX_SCALE_F   0x1p52f
#define FIX_INV_F     0x1p-52f

// ---------------- f32x2 packed-FMA helpers ----------------
__device__ __forceinline__ void ffma2(unsigned long long& d, unsigned long long a,
                                      unsigned long long b) {
    asm("fma.rn.f32x2 %0, %1, %2, %0;" : "+l"(d) : "l"(a), "l"(b));
}
__device__ __forceinline__ unsigned long long pack2(float x, float y) {
    unsigned long long r;
    asm("mov.b64 %0, {%1, %2};" : "=l"(r) : "f"(x), "f"(y));
    return r;
}
__device__ __forceinline__ float2 unpack2(unsigned long long v) {
    float2 r;
    asm("mov.b64 {%0, %1}, %2;" : "=f"(r.x), "=f"(r.y) : "l"(v));
    return r;
}

// ---------------- K1: edge weights + integer degree sums ----------------
__global__ void k_edge_w(const float* __restrict__ ef, const float* __restrict__ Wef,
                         const float* __restrict__ bef,
                         const int* __restrict__ src, const int* __restrict__ dst, int E) {
    int e = blockIdx.x * blockDim.x + threadIdx.x;
    if (e >= E) return;
    const float4* p = (const float4*)(ef + (size_t)e * 16);
    float acc = __ldg(bef);
#pragma unroll
    for (int q = 0; q < 4; q++) {
        float4 v = __ldg(p + q);
        acc += v.x * __ldg(Wef + q * 4 + 0) + v.y * __ldg(Wef + q * 4 + 1)
             + v.z * __ldg(Wef + q * 4 + 2) + v.w * __ldg(Wef + q * 4 + 3);
    }
    g_wraw[e] = acc;
    unsigned long long fx = __float2ull_rn(acc * FIX_SCALE_F);  // w > 0 by construction
    int s = src[e], d = dst[e];
    atomicAdd(&g_doutw64[s], fx);
    atomicAdd(&g_dinw64[d],  fx);
    atomicAdd(&g_cntout[s], 1);
    atomicAdd(&g_cntin[d],  1);
}

// ---------------- K2a: per-block reduce of in-degrees ----------------
__global__ __launch_bounds__(SCAN_BLK)
void k_scan_p1(int N) {
    __shared__ int wsum[32];
    int tid = threadIdx.x;
    int i = blockIdx.x * SCAN_BLK + tid;
    int v = (i < N) ? g_cntin[i] : 0;
#pragma unroll
    for (int o = 16; o > 0; o >>= 1) v += __shfl_down_sync(0xffffffffu, v, o);
    if ((tid & 31) == 0) wsum[tid >> 5] = v;
    __syncthreads();
    if (tid < 32) {
        int x = wsum[tid];
#pragma unroll
        for (int o = 16; o > 0; o >>= 1) x += __shfl_down_sync(0xffffffffu, x, o);
        if (tid == 0) g_blocksum[blockIdx.x] = x;
    }
}

// ---------------- K2b: block-local scan + global offsets + node scales ----------------
__global__ __launch_bounds__(SCAN_BLK)
void k_scan_p2(int N, int E) {
    __shared__ int bsum[128];      // scanned block sums (inclusive)
    __shared__ int warpsums[32];
    int tid = threadIdx.x;
    int lane = tid & 31, wid = tid >> 5;

    if (tid < 128) bsum[tid] = (tid < NBLK_SCAN) ? g_blocksum[tid] : 0;
    __syncthreads();
    // Hillis-Steele over 128 entries
    for (int o = 1; o < 128; o <<= 1) {
        int v = (tid < 128 && tid >= o) ? bsum[tid - o] : 0;
        __syncthreads();
        if (tid < 128) bsum[tid] += v;
        __syncthreads();
    }
    int block_off = (blockIdx.x > 0) ? bsum[blockIdx.x - 1] : 0;

    int i = blockIdx.x * SCAN_BLK + tid;
    int v = (i < N) ? g_cntin[i] : 0;
    int x = v;
#pragma unroll
    for (int o = 1; o < 32; o <<= 1) {
        int y = __shfl_up_sync(0xffffffffu, x, o);
        if (lane >= o) x += y;
    }
    if (lane == 31) warpsums[wid] = x;
    __syncthreads();
    if (wid == 0) {
        int w = warpsums[lane];
#pragma unroll
        for (int o = 1; o < 32; o <<= 1) {
            int y = __shfl_up_sync(0xffffffffu, w, o);
            if (lane >= o) w += y;
        }
        warpsums[lane] = w;
    }
    __syncthreads();
    int excl = (x - v) + (wid > 0 ? warpsums[wid - 1] : 0) + block_off;

    if (i < N) {
        g_rowstart[i] = excl;
        g_cursor[i]   = excl;
        int cout = g_cntout[i];
        float dw = __ull2float_rn(g_doutw64[i]) * FIX_INV_F;
        float iw = __ull2float_rn(g_dinw64[i])  * FIX_INV_F;
        float rdo = dw > 0.f ? rsqrtf(dw) : 0.f;
        float rdi = iw > 0.f ? rsqrtf(iw) : 0.f;
        g_srcscale[i] = rdo * rsqrtf((float)(cout > 1 ? cout : 1));
        g_dscale[i]   = rdi * rsqrtf((float)(v > 1 ? v : 1));
    }
    if (blockIdx.x == 0 && tid == 0) g_rowstart[N] = E;
}

// ---------------- K3: fill CSR (bare atomic scatter; no fences) ----------------
__global__ void k_fill(const int* __restrict__ src, const int* __restrict__ dst, int E) {
    int e = blockIdx.x * blockDim.x + threadIdx.x;
    if (e >= E) return;
    int s = src[e], d = dst[e];
    float w = g_wraw[e] * __ldg(&g_srcscale[s]);
    unsigned long long key = ((unsigned long long)(unsigned)s << 32)
                           | (unsigned)__float_as_int(w);
    int pos = atomicAdd(&g_cursor[d], 1);
    g_csr[pos] = key;
}

// ---------------- K4: canonical per-row sort (thread per node, in place) ----------
// CSR row content becomes deterministic even though atomic fill order is not.
__global__ void k_sort(int N) {
    int n = blockIdx.x * blockDim.x + threadIdx.x;
    if (n >= N) return;
    int r0 = g_rowstart[n], r1 = g_rowstart[n + 1];
    for (int j = r0 + 1; j < r1; j++) {
        unsigned long long k = g_csr[j];
        int t = j - 1;
        while (t >= r0 && g_csr[t] > k) { g_csr[t + 1] = g_csr[t]; t--; }
        g_csr[t + 1] = k;
    }
}

// ---------------- K5: warp-per-node CSR aggregation (plain float; CSR canonical) ----
__global__ __launch_bounds__(256)
void k_agg(const float* __restrict__ H, float* __restrict__ OUT, int N) {
    int gw = (blockIdx.x * blockDim.x + threadIdx.x) >> 5;
    if (gw >= N) return;
    int lane = threadIdx.x & 31;
    int i0 = __ldg(&g_rowstart[gw]), i1 = __ldg(&g_rowstart[gw + 1]);

    float a0 = 0.f, a1 = 0.f, a2 = 0.f, a3 = 0.f;
    int i = i0;
    for (; i + 1 < i1; i += 2) {
        unsigned long long kA = __ldg(&g_csr[i]);
        unsigned long long kB = __ldg(&g_csr[i + 1]);
        float wA = __int_as_float((int)(unsigned)kA);
        float wB = __int_as_float((int)(unsigned)kB);
        float4 hA = __ldg((const float4*)(H + ((size_t)(kA >> 32)) * F) + lane);
        float4 hB = __ldg((const float4*)(H + ((size_t)(kB >> 32)) * F) + lane);
        a0 += wA * hA.x; a1 += wA * hA.y; a2 += wA * hA.z; a3 += wA * hA.w;
        a0 += wB * hB.x; a1 += wB * hB.y; a2 += wB * hB.z; a3 += wB * hB.w;
    }
    if (i < i1) {
        unsigned long long kA = __ldg(&g_csr[i]);
        float wA = __int_as_float((int)(unsigned)kA);
        float4 hA = __ldg((const float4*)(H + ((size_t)(kA >> 32)) * F) + lane);
        a0 += wA * hA.x; a1 += wA * hA.y; a2 += wA * hA.z; a3 += wA * hA.w;
    }
    float sc = __ldg(&g_dscale[gw]);
    float4 o; o.x = a0 * sc; o.y = a1 * sc; o.z = a2 * sc; o.w = a3 * sc;
    *(float4*)(OUT + (size_t)gw * F + lane * 4) = o;
}

// ---------------- K6: GEMM  C = A @ W (+bias, optional relu) via packed f32x2 FMA ----
template <int RELU>
__global__ __launch_bounds__(256)
void k_gemm(const float* __restrict__ A, const float* __restrict__ W,
            const float* __restrict__ bias, float* __restrict__ C, int N) {
    __shared__ float As[16][68];
    __shared__ float Bs[16][128];

    int tid = threadIdx.x;
    int block_row = blockIdx.x * 64;
    int tx = tid & 31;
    int ty = tid >> 5;

    int am = tid >> 2;
    int ak = (tid & 3) * 4;
    int bk = tid >> 5;
    int bj = (tid & 31) * 4;

    unsigned long long accp[4][4];
#pragma unroll
    for (int p = 0; p < 4; p++)
#pragma unroll
        for (int c = 0; c < 4; c++) accp[p][c] = 0ull;

    for (int k0 = 0; k0 < 128; k0 += 16) {
        int arow = block_row + am;
        float4 av = make_float4(0.f, 0.f, 0.f, 0.f);
        if (arow < N) av = *(const float4*)(A + (size_t)arow * F + k0 + ak);
        As[ak + 0][am] = av.x; As[ak + 1][am] = av.y;
        As[ak + 2][am] = av.z; As[ak + 3][am] = av.w;

        *(float4*)&Bs[bk][bj]     = *(const float4*)(W + (size_t)(k0 + bk) * F + bj);
        *(float4*)&Bs[bk + 8][bj] = *(const float4*)(W + (size_t)(k0 + bk + 8) * F + bj);
        __syncthreads();

#pragma unroll
        for (int kk = 0; kk < 16; kk++) {
            const float* arp = &As[kk][ty * 8];
            ulonglong2 ap0 = *(const ulonglong2*)(arp);
            ulonglong2 ap1 = *(const ulonglong2*)(arp + 4);
            float4 bv = *(const float4*)&Bs[kk][tx * 4];
            unsigned long long b0 = pack2(bv.x, bv.x);
            unsigned long long b1 = pack2(bv.y, bv.y);
            unsigned long long b2 = pack2(bv.z, bv.z);
            unsigned long long b3 = pack2(bv.w, bv.w);
            ffma2(accp[0][0], ap0.x, b0); ffma2(accp[0][1], ap0.x, b1);
            ffma2(accp[0][2], ap0.x, b2); ffma2(accp[0][3], ap0.x, b3);
            ffma2(accp[1][0], ap0.y, b0); ffma2(accp[1][1], ap0.y, b1);
            ffma2(accp[1][2], ap0.y, b2); ffma2(accp[1][3], ap0.y, b3);
            ffma2(accp[2][0], ap1.x, b0); ffma2(accp[2][1], ap1.x, b1);
            ffma2(accp[2][2], ap1.x, b2); ffma2(accp[2][3], ap1.x, b3);
            ffma2(accp[3][0], ap1.y, b0); ffma2(accp[3][1], ap1.y, b1);
            ffma2(accp[3][2], ap1.y, b2); ffma2(accp[3][3], ap1.y, b3);
        }
        __syncthreads();
    }

    float4 bv = __ldg((const float4*)(bias) + tx);
#pragma unroll
    for (int p = 0; p < 4; p++) {
        float2 c0 = unpack2(accp[p][0]);
        float2 c1 = unpack2(accp[p][1]);
        float2 c2 = unpack2(accp[p][2]);
        float2 c3 = unpack2(accp[p][3]);
        int row0 = block_row + ty * 8 + 2 * p;
        float4 o0, o1;
        o0.x = c0.x + bv.x; o0.y = c1.x + bv.y; o0.z = c2.x + bv.z; o0.w = c3.x + bv.w;
        o1.x = c0.y + bv.x; o1.y = c1.y + bv.y; o1.z = c2.y + bv.z; o1.w = c3.y + bv.w;
        if (RELU) {
            o0.x = fmaxf(o0.x, 0.f); o0.y = fmaxf(o0.y, 0.f);
            o0.z = fmaxf(o0.z, 0.f); o0.w = fmaxf(o0.w, 0.f);
            o1.x = fmaxf(o1.x, 0.f); o1.y = fmaxf(o1.y, 0.f);
            o1.z = fmaxf(o1.z, 0.f); o1.w = fmaxf(o1.w, 0.f);
        }
        if (row0 < N)     *(float4*)(C + (size_t)row0 * F + tx * 4) = o0;
        if (row0 + 1 < N) *(float4*)(C + (size_t)(row0 + 1) * F + tx * 4) = o1;
    }
}

// ---------------- K7: trailing zero (prepares counters for the NEXT replay) ----------
__global__ void k_zero_tail(int N) {
    int i = blockIdx.x * blockDim.x + threadIdx.x;
    if (i < N) {
        g_doutw64[i] = 0ull; g_dinw64[i] = 0ull;
        g_cntin[i] = 0; g_cntout[i] = 0;
    }
}

// ---------------- host ----------------
extern "C" void kernel_launch(void* const* d_in, const int* in_sizes, int n_in,
                              void* d_out, int out_size) {
    const float* node_feats = (const float*)d_in[0];
    const float* edge_feats = (const float*)d_in[1];
    const float* W_ef       = (const float*)d_in[2];
    const float* b_ef       = (const float*)d_in[3];
    const float* W1         = (const float*)d_in[4];
    const float* b1         = (const float*)d_in[5];
    const float* W2         = (const float*)d_in[6];
    const float* b2         = (const float*)d_in[7];
    const int*   src        = (const int*)d_in[8];
    const int*   dst        = (const int*)d_in[9];
    int N = in_sizes[0] / F;
    int E = in_sizes[8];
    float* out = (float*)d_out;

    float *pa1, *ph1, *pa2;
    cudaGetSymbolAddress((void**)&pa1, g_a1);
    cudaGetSymbolAddress((void**)&ph1, g_h1);
    cudaGetSymbolAddress((void**)&pa2, g_a2);

    int nbN = (N + 255) / 256;
    int nbE = (E + 255) / 256;
    int nbG = (N + 63) / 64;
    int nbA = (N * 32 + 255) / 256;
    int nbS = (N + SCAN_BLK - 1) / SCAN_BLK;

    k_edge_w   <<<nbE, 256>>>(edge_feats, W_ef, b_ef, src, dst, E); // 0
    k_scan_p1  <<<nbS, SCAN_BLK>>>(N);                              // 1
    k_scan_p2  <<<nbS, SCAN_BLK>>>(N, E);                           // 2
    k_fill     <<<nbE, 256>>>(src, dst, E);                         // 3  <- profiled
    k_sort     <<<nbN, 256>>>(N);                                   // 4
    k_agg      <<<nbA, 256>>>(node_feats, pa1, N);                  // 5
    k_gemm<1>  <<<nbG, 256>>>(pa1, W1, b1, ph1, N);                 // 6
    k_agg      <<<nbA, 256>>>(ph1, pa2, N);                         // 7
    k_gemm<0>  <<<nbG, 256>>>(pa2, W2, b2, out, N);                 // 8
    k_zero_tail<<<nbN, 256>>>(N);                                   // 9
}